// round 8
// baseline (speedup 1.0000x reference)
#include <cuda_runtime.h>
#include <cuda_bf16.h>
#include <math.h>
#include <stdint.h>

#define BSZn   2
#define SEQn   512
#define DMODEL 768
#define DINNER 1536
#define NHEADSn 24
#define HEADDIMn 64
#define DSTATEn 64
#define CONVDIM 1664
#define DIP    3224
#define BT     (BSZn*SEQn)   // 1024
#define DFF    3072
#define EPSV   1e-5f

typedef __nv_bfloat16 bf16;

// ---------------- scratch ----------------
__device__ float g_zx  [BT*DIP];
__device__ float g_xbcf[BT*CONVDIM];
__device__ float g_xbcb[BT*CONVDIM];
__device__ float g_dtp [BT*NHEADSn];
__device__ float g_dAe [BT*NHEADSn];
__device__ float g_yf  [BT*DINNER];
__device__ float g_yb  [BT*DINNER];
__device__ float g_mi  [BT*DMODEL];
// bf16 hi/lo activation planes
__device__ __align__(16) bf16 g_xnh [BT*DMODEL],  g_xnl [BT*DMODEL];
__device__ __align__(16) bf16 g_ysh [BT*DINNER],  g_ysl [BT*DINNER];
__device__ __align__(16) bf16 g_mh  [BT*DMODEL],  g_ml  [BT*DMODEL];
__device__ __align__(16) bf16 g_h1h [BT*DFF],     g_h1l [BT*DFF];
// bf16 hi/lo weight planes
__device__ __align__(16) bf16 g_wip_h[DIP*DMODEL],   g_wip_l[DIP*DMODEL];
__device__ __align__(16) bf16 g_wop_h[DMODEL*DINNER], g_wop_l[DMODEL*DINNER];
__device__ __align__(16) bf16 g_w1_h [DFF*DMODEL],   g_w1_l [DFF*DMODEL];
__device__ __align__(16) bf16 g_w2_h [DMODEL*DFF],   g_w2_l [DMODEL*DFF];

// ---------------- helpers ----------------
__device__ __forceinline__ float warp_sum(float v) {
    #pragma unroll
    for (int o = 16; o > 0; o >>= 1) v += __shfl_xor_sync(0xffffffffu, v, o);
    return v;
}
__device__ __forceinline__ float siluf(float x) { return x / (1.f + expf(-x)); }
__device__ __forceinline__ float geluf(float x) { return 0.5f * x * (1.f + erff(x * 0.70710678118654752f)); }

__device__ __forceinline__ uint32_t smem_u32(const void* p) {
    uint32_t a;
    asm("{ .reg .u64 t; cvta.to.shared.u64 t, %1; cvt.u32.u64 %0, t; }" : "=r"(a) : "l"(p));
    return a;
}
__device__ __forceinline__ void mma_bf16(float* c, const uint32_t* a, const uint32_t* b) {
    asm volatile(
        "mma.sync.aligned.m16n8k16.row.col.f32.bf16.bf16.f32 "
        "{%0,%1,%2,%3},{%4,%5,%6,%7},{%8,%9},{%0,%1,%2,%3};"
        : "+f"(c[0]), "+f"(c[1]), "+f"(c[2]), "+f"(c[3])
        : "r"(a[0]), "r"(a[1]), "r"(a[2]), "r"(a[3]), "r"(b[0]), "r"(b[1]));
}
__device__ __forceinline__ void ldsm4(uint32_t* r, uint32_t addr) {
    asm volatile("ldmatrix.sync.aligned.m8n8.x4.shared.b16 {%0,%1,%2,%3}, [%4];"
                 : "=r"(r[0]), "=r"(r[1]), "=r"(r[2]), "=r"(r[3]) : "r"(addr));
}
__device__ __forceinline__ void cpasync16(uint32_t dst, const void* src, uint32_t ssz) {
    asm volatile("cp.async.cg.shared.global [%0], [%1], 16, %2;"
                 :: "r"(dst), "l"(src), "r"(ssz) : "memory");
}
__device__ __forceinline__ void cp_commit() {
    asm volatile("cp.async.commit_group;" ::: "memory");
}
template<int Np>
__device__ __forceinline__ void cp_wait() {
    asm volatile("cp.async.wait_group %0;" :: "n"(Np) : "memory");
}
__device__ __forceinline__ void split1(float x, bf16& h, bf16& l) {
    h = __float2bfloat16_rn(x);
    l = __float2bfloat16_rn(x - __bfloat162float(h));
}

// ---------------- weight hi/lo split ----------------
__global__ void wsplit_kernel(const float* __restrict__ w, bf16* __restrict__ wh,
                              bf16* __restrict__ wl, int n4) {
    int i = blockIdx.x * blockDim.x + threadIdx.x;
    if (i >= n4) return;
    float4 v = reinterpret_cast<const float4*>(w)[i];
    bf16 h0, h1, h2, h3, l0, l1, l2, l3;
    split1(v.x, h0, l0); split1(v.y, h1, l1);
    split1(v.z, h2, l2); split1(v.w, h3, l3);
    __nv_bfloat162 hp0; hp0.x = h0; hp0.y = h1;
    __nv_bfloat162 hp1; hp1.x = h2; hp1.y = h3;
    __nv_bfloat162 lp0; lp0.x = l0; lp0.y = l1;
    __nv_bfloat162 lp1; lp1.x = l2; lp1.y = l3;
    uint2 hh = make_uint2(*reinterpret_cast<uint32_t*>(&hp0), *reinterpret_cast<uint32_t*>(&hp1));
    uint2 ll = make_uint2(*reinterpret_cast<uint32_t*>(&lp0), *reinterpret_cast<uint32_t*>(&lp1));
    reinterpret_cast<uint2*>(wh)[i] = hh;
    reinterpret_cast<uint2*>(wl)[i] = ll;
}

// ---------------- LayerNorm -> bf16 hi/lo planes ----------------
__global__ void ln_hl_kernel(const float* __restrict__ in, const float* __restrict__ w,
                             const float* __restrict__ b,
                             bf16* __restrict__ oh, bf16* __restrict__ ol) {
    int row = blockIdx.x;
    int tid = threadIdx.x;
    const float* x = in + (long)row * DMODEL;
    float v[3], s = 0.f, ss = 0.f;
    #pragma unroll
    for (int i = 0; i < 3; i++) {
        v[i] = x[tid + i * 256];
        s += v[i]; ss += v[i] * v[i];
    }
    __shared__ float sr[8], sr2[8], bres[2];
    float ws = warp_sum(s), ws2 = warp_sum(ss);
    int lane = tid & 31, wid = tid >> 5;
    if (lane == 0) { sr[wid] = ws; sr2[wid] = ws2; }
    __syncthreads();
    if (tid == 0) {
        float a = 0.f, c = 0.f;
        #pragma unroll
        for (int i = 0; i < 8; i++) { a += sr[i]; c += sr2[i]; }
        bres[0] = a; bres[1] = c;
    }
    __syncthreads();
    float mu  = bres[0] * (1.f / DMODEL);
    float var = bres[1] * (1.f / DMODEL) - mu * mu;
    float r = rsqrtf(var + EPSV);
    #pragma unroll
    for (int i = 0; i < 3; i++) {
        int c = tid + i * 256;
        float o = (v[i] - mu) * r * w[c] + b[c];
        bf16 h, l; split1(o, h, l);
        oh[(long)row * DMODEL + c] = h;
        ol[(long)row * DMODEL + c] = l;
    }
}

// ======= GEMM (pre-split bf16 hi/lo, cp.async x3, ldmatrix, HMMA 3-product) ==
// C[M,N] = A[M,K] @ W[N,K]^T. CTA tile 128x64, BK=32, 8 warps (4M x 2N).
// EPI: 0=none, 1=gelu(v+bias), 2=v+bias+resid. OUTHL: 1 -> write Ch/Cl planes.
#define RS 80
#define A_PL (128 * RS)          // 10240
#define B_PL (64 * RS)           // 5120
#define STG  (2 * A_PL + 2 * B_PL) // 30720
#define GEMM_SMEM (3 * STG)      // 92160

template<int EPI, int OUTHL>
__global__ void __launch_bounds__(256, 2) gemm_bf16p(
        const bf16* __restrict__ Ah_, const bf16* __restrict__ Al_,
        const bf16* __restrict__ Wh_, const bf16* __restrict__ Wl_,
        const float* __restrict__ bias, const float* __restrict__ resid,
        float* __restrict__ C, bf16* __restrict__ Ch, bf16* __restrict__ Cl,
        int M, int N, int K) {
    extern __shared__ char smem[];
    uint32_t sb = smem_u32(smem);
    const int tid = threadIdx.x;
    const int lane = tid & 31, wid = tid >> 5;
    const int warpM = wid & 3, warpN = wid >> 2;
    const int row0 = blockIdx.y * 128;
    const int col0 = blockIdx.x * 64;
    const int quad = lane >> 3, r8 = lane & 7;
    const int g = lane >> 2, tg = lane & 3;

    float acc[2][4][4];
    #pragma unroll
    for (int mt = 0; mt < 2; mt++)
        #pragma unroll
        for (int nt = 0; nt < 4; nt++)
            #pragma unroll
            for (int i = 0; i < 4; i++) acc[mt][nt][i] = 0.f;

    const int ar0 = tid >> 2,          ac0 = tid & 3;
    const int ar1 = (tid + 256) >> 2,  ac1 = ac0;
    const int br  = tid >> 2,          bc  = tid & 3;
    const int bn  = col0 + br;
    const int bnc = bn < N ? bn : (N - 1);
    const uint32_t bsz = bn < N ? 16u : 0u;

    auto issue = [&](int kt, int st) {
        uint32_t base = sb + st * STG;
        int k0 = kt * 32;
        cpasync16(base + ar0 * RS + ac0 * 16,        &Ah_[(long)(row0 + ar0) * K + k0 + ac0 * 8], 16);
        cpasync16(base + A_PL + ar0 * RS + ac0 * 16, &Al_[(long)(row0 + ar0) * K + k0 + ac0 * 8], 16);
        cpasync16(base + ar1 * RS + ac1 * 16,        &Ah_[(long)(row0 + ar1) * K + k0 + ac1 * 8], 16);
        cpasync16(base + A_PL + ar1 * RS + ac1 * 16, &Al_[(long)(row0 + ar1) * K + k0 + ac1 * 8], 16);
        cpasync16(base + 2 * A_PL + br * RS + bc * 16,        &Wh_[(long)bnc * K + k0 + bc * 8], bsz);
        cpasync16(base + 2 * A_PL + B_PL + br * RS + bc * 16, &Wl_[(long)bnc * K + k0 + bc * 8], bsz);
        cp_commit();
    };

    const int ntiles = K / 32;
    issue(0, 0);
    issue(1, 1);

    for (int kt = 0; kt < ntiles; kt++) {
        cp_wait<1>();
        __syncthreads();
        if (kt + 2 < ntiles) issue(kt + 2, (kt + 2) % 3);
        else cp_commit();

        uint32_t base = sb + (kt % 3) * STG;
        uint32_t pAh = base, pAl = base + A_PL;
        uint32_t pBh = base + 2 * A_PL, pBl = pBh + B_PL;
        #pragma unroll
        for (int slab = 0; slab < 2; slab++) {
            uint32_t kbA = slab * 32 + (quad >> 1) * 16;
            uint32_t kbB = slab * 32 + (quad & 1) * 16;
            uint32_t ah[2][4], al[2][4], bh[2][4], bl[2][4];
            #pragma unroll
            for (int mt = 0; mt < 2; mt++) {
                uint32_t ra = (uint32_t)((warpM * 32 + mt * 16 + (quad & 1) * 8 + r8) * RS) + kbA;
                ldsm4(ah[mt], pAh + ra);
                ldsm4(al[mt], pAl + ra);
            }
            #pragma unroll
            for (int nt16 = 0; nt16 < 2; nt16++) {
                uint32_t rb = (uint32_t)((warpN * 32 + nt16 * 16 + (quad >> 1) * 8 + r8) * RS) + kbB;
                ldsm4(bh[nt16], pBh + rb);
                ldsm4(bl[nt16], pBl + rb);
            }
            #pragma unroll
            for (int mt = 0; mt < 2; mt++)
                #pragma unroll
                for (int nt16 = 0; nt16 < 2; nt16++) {
                    mma_bf16(acc[mt][nt16 * 2 + 0], ah[mt], &bl[nt16][0]);
                    mma_bf16(acc[mt][nt16 * 2 + 0], al[mt], &bh[nt16][0]);
                    mma_bf16(acc[mt][nt16 * 2 + 0], ah[mt], &bh[nt16][0]);
                    mma_bf16(acc[mt][nt16 * 2 + 1], ah[mt], &bl[nt16][2]);
                    mma_bf16(acc[mt][nt16 * 2 + 1], al[mt], &bh[nt16][2]);
                    mma_bf16(acc[mt][nt16 * 2 + 1], ah[mt], &bh[nt16][2]);
                }
        }
    }

    #pragma unroll
    for (int mt = 0; mt < 2; mt++) {
        int rbase = row0 + warpM * 32 + mt * 16 + g;
        #pragma unroll
        for (int nt = 0; nt < 4; nt++) {
            int col = col0 + warpN * 32 + nt * 8 + tg * 2;
            if (col < N) {
                float2 v0 = make_float2(acc[mt][nt][0], acc[mt][nt][1]);
                float2 v1 = make_float2(acc[mt][nt][2], acc[mt][nt][3]);
                if (EPI == 1) {
                    float b0 = bias[col], b1 = bias[col + 1];
                    v0.x = geluf(v0.x + b0); v0.y = geluf(v0.y + b1);
                    v1.x = geluf(v1.x + b0); v1.y = geluf(v1.y + b1);
                }
                if (EPI == 2) {
                    float b0 = bias[col], b1 = bias[col + 1];
                    float2 r0 = *reinterpret_cast<const float2*>(&resid[(long)rbase * N + col]);
                    float2 r1 = *reinterpret_cast<const float2*>(&resid[(long)(rbase + 8) * N + col]);
                    v0.x += b0 + r0.x; v0.y += b1 + r0.y;
                    v1.x += b0 + r1.x; v1.y += b1 + r1.y;
                }
                if (OUTHL) {
                    bf16 h0, h1, l0, l1;
                    split1(v0.x, h0, l0); split1(v0.y, h1, l1);
                    __nv_bfloat162 hp; hp.x = h0; hp.y = h1;
                    __nv_bfloat162 lp; lp.x = l0; lp.y = l1;
                    *reinterpret_cast<uint32_t*>(&Ch[(long)rbase * N + col]) = *reinterpret_cast<uint32_t*>(&hp);
                    *reinterpret_cast<uint32_t*>(&Cl[(long)rbase * N + col]) = *reinterpret_cast<uint32_t*>(&lp);
                    split1(v1.x, h0, l0); split1(v1.y, h1, l1);
                    hp.x = h0; hp.y = h1; lp.x = l0; lp.y = l1;
                    *reinterpret_cast<uint32_t*>(&Ch[(long)(rbase + 8) * N + col]) = *reinterpret_cast<uint32_t*>(&hp);
                    *reinterpret_cast<uint32_t*>(&Cl[(long)(rbase + 8) * N + col]) = *reinterpret_cast<uint32_t*>(&lp);
                } else {
                    *reinterpret_cast<float2*>(&C[(long)rbase * N + col])       = v0;
                    *reinterpret_cast<float2*>(&C[(long)(rbase + 8) * N + col]) = v1;
                }
            }
        }
    }
}

// ---------------- depthwise conv (causal fwd + anti-causal bwd) + SiLU --------
__global__ void conv_kernel(const float* __restrict__ zx, const float* __restrict__ cw,
                            const float* __restrict__ cb,
                            float* __restrict__ xf, float* __restrict__ xb) {
    long idx = (long)blockIdx.x * blockDim.x + threadIdx.x;
    if (idx >= (long)BT * CONVDIM) return;
    int c = (int)(idx % CONVDIM);
    long bt = idx / CONVDIM;
    int t = (int)(bt % SEQn);
    int b = (int)(bt / SEQn);
    float w0 = cw[c*4+0], w1 = cw[c*4+1], w2 = cw[c*4+2], w3 = cw[c*4+3];
    float bias = cb[c];
    const float* base = zx + ((long)b * SEQn) * DIP + DINNER + c;
    float af = bias;
    if (t >= 3) af += w0 * base[(long)(t-3) * DIP];
    if (t >= 2) af += w1 * base[(long)(t-2) * DIP];
    if (t >= 1) af += w2 * base[(long)(t-1) * DIP];
    af += w3 * base[(long)t * DIP];
    xf[idx] = siluf(af);
    float ab = bias;
    if (t + 3 < SEQn) ab += w0 * base[(long)(t+3) * DIP];
    if (t + 2 < SEQn) ab += w1 * base[(long)(t+2) * DIP];
    if (t + 1 < SEQn) ab += w2 * base[(long)(t+1) * DIP];
    ab += w3 * base[(long)t * DIP];
    xb[idx] = siluf(ab);
}

// ---------------- dt processing ----------------
__global__ void dt_kernel(const float* __restrict__ zx, const float* __restrict__ dt_bias,
                          const float* __restrict__ A_log,
                          float* __restrict__ dtp, float* __restrict__ dAe) {
    int idx = blockIdx.x * blockDim.x + threadIdx.x;
    if (idx >= BT * NHEADSn) return;
    int h = idx % NHEADSn;
    long row = idx / NHEADSn;
    float d = zx[row * DIP + DINNER + CONVDIM + h] + dt_bias[h];
    float sp = (d > 20.f) ? d : log1pf(expf(d));
    dtp[idx] = sp;
    dAe[idx] = expf(-expf(A_log[h]) * sp);
}

// --------- SSM scan: 256 thr, 2-step-ahead pipeline, 4 yv chains -------------
__global__ void scan_kernel(const float* __restrict__ xbcf, const float* __restrict__ xbcb,
                            const float* __restrict__ dtp, const float* __restrict__ dAe,
                            const float* __restrict__ Dp_,
                            float* __restrict__ yf, float* __restrict__ yb) {
    int blk = blockIdx.x;
    int dir = blk / (BSZn * NHEADSn);
    int rem = blk % (BSZn * NHEADSn);
    int b = rem / NHEADSn, hh = rem % NHEADSn;
    const float* xBC = dir ? xbcb : xbcf;
    float* y = dir ? yb : yf;
    int tid = threadIdx.x;
    int p = tid >> 2, q = tid & 3;
    float hst[16];
    #pragma unroll
    for (int n = 0; n < 16; n++) hst[n] = 0.f;
    __shared__ float sB[2][DSTATEn], sC[2][DSTATEn];
    float Dv = Dp_[hh];
    int ldpos = ((tid & 15) * 4 + ((tid >> 4) & 3));

    // preload steps 0 and 1
    float B1 = 0.f, C1 = 0.f, x0, dt0, dA0, x1, dt1, dA1;
    long crow_cur, rown;
    {
        int t0 = dir ? (SEQn - 1) : 0;
        crow_cur = (long)b * SEQn + t0;
        const float* xr = xBC + crow_cur * CONVDIM;
        float B0 = 0.f, C0 = 0.f;
        if (tid < 64)       B0 = xr[DINNER + tid];
        else if (tid < 128) C0 = xr[DINNER + tid];
        x0 = xr[hh * HEADDIMn + p];
        dt0 = dtp[crow_cur * NHEADSn + hh];
        dA0 = dAe[crow_cur * NHEADSn + hh];
        int t1 = dir ? (SEQn - 2) : 1;
        rown = (long)b * SEQn + t1;
        const float* xr1 = xBC + rown * CONVDIM;
        if (tid < 64)       B1 = xr1[DINNER + tid];
        else if (tid < 128) C1 = xr1[DINNER + tid];
        x1 = xr1[hh * HEADDIMn + p];
        dt1 = dtp[rown * NHEADSn + hh];
        dA1 = dAe[rown * NHEADSn + hh];
        if (tid < 64)       sB[0][ldpos] = B0;
        else if (tid < 128) sC[0][ldpos] = C0;
    }

    for (int s = 0; s < SEQn; s++) {
        __syncthreads();
        // store step s+1 B/C into slot (s+1)&1 (its last readers finished before this barrier)
        if (s + 1 < SEQn) {
            if (tid < 64)       sB[(s + 1) & 1][ldpos] = B1;
            else if (tid < 128) sC[(s + 1) & 1][ldpos] = C1;
        }
        float cx = x0, cdt = dt0, cdA = dA0;
        long crow = crow_cur;
        x0 = x1; dt0 = dt1; dA0 = dA1; crow_cur = rown;
        // issue loads for step s+2 (consumed two barriers later)
        if (s + 2 < SEQn) {
            int t2 = dir ? (SEQn - 3 - s) : (s + 2);
            rown = (long)b * SEQn + t2;
            const float* xr2 = xBC + rown * CONVDIM;
            if (tid < 64)       B1 = xr2[DINNER + tid];
            else if (tid < 128) C1 = xr2[DINNER + tid];
            x1 = xr2[hh * HEADDIMn + p];
            dt1 = dtp[rown * NHEADSn + hh];
            dA1 = dAe[rown * NHEADSn + hh];
        }
        int buf = s & 1;
        float c1 = cdt * cx;
        float yv0 = (q == 0) ? Dv * cx : 0.f;
        float yv1 = 0.f, yv2 = 0.f, yv3 = 0.f;
        #pragma unroll
        for (int n = 0; n < 16; n += 4) {
            int p0 = n * 4 + q;
            hst[n]     = cdA * hst[n]     + c1 * sB[buf][p0];      yv0 += hst[n]     * sC[buf][p0];
            hst[n + 1] = cdA * hst[n + 1] + c1 * sB[buf][p0 + 4];  yv1 += hst[n + 1] * sC[buf][p0 + 4];
            hst[n + 2] = cdA * hst[n + 2] + c1 * sB[buf][p0 + 8];  yv2 += hst[n + 2] * sC[buf][p0 + 8];
            hst[n + 3] = cdA * hst[n + 3] + c1 * sB[buf][p0 + 12]; yv3 += hst[n + 3] * sC[buf][p0 + 12];
        }
        float yv = (yv0 + yv1) + (yv2 + yv3);
        yv += __shfl_xor_sync(0xffffffffu, yv, 1);
        yv += __shfl_xor_sync(0xffffffffu, yv, 2);
        if (q == 0) y[crow * DINNER + hh * HEADDIMn + p] = yv;
    }
}

// ------ gate + RMSNorm + sum -> bf16 hi/lo planes ----------------
__global__ void gatenorm_kernel(const float* __restrict__ yf, const float* __restrict__ yb,
                                const float* __restrict__ zx, const float* __restrict__ nw,
                                bf16* __restrict__ oh, bf16* __restrict__ ol) {
    int row = blockIdx.x;
    int tid = threadIdx.x;
    const float* z = zx + (long)row * DIP;
    float gf[6], gb[6], ssf = 0.f, ssb = 0.f;
    #pragma unroll
    for (int i = 0; i < 6; i++) {
        int c = tid + i * 256;
        float s = siluf(z[c]);
        float a = yf[(long)row * DINNER + c] * s;
        float d = yb[(long)row * DINNER + c] * s;
        gf[i] = a; gb[i] = d;
        ssf += a * a; ssb += d * d;
    }
    __shared__ float r1[8], r2[8], bres[2];
    float w1 = warp_sum(ssf), w2 = warp_sum(ssb);
    int lane = tid & 31, wid = tid >> 5;
    if (lane == 0) { r1[wid] = w1; r2[wid] = w2; }
    __syncthreads();
    if (tid == 0) {
        float a = 0.f, c = 0.f;
        #pragma unroll
        for (int i = 0; i < 8; i++) { a += r1[i]; c += r2[i]; }
        bres[0] = a; bres[1] = c;
    }
    __syncthreads();
    float rf = rsqrtf(bres[0] * (1.f / DINNER) + EPSV);
    float rb = rsqrtf(bres[1] * (1.f / DINNER) + EPSV);
    #pragma unroll
    for (int i = 0; i < 6; i++) {
        int c = tid + i * 256;
        float o = (gf[i] * rf + gb[i] * rb) * nw[c];
        bf16 h, l; split1(o, h, l);
        oh[(long)row * DINNER + c] = h;
        ol[(long)row * DINNER + c] = l;
    }
}

// ---------------- launch ----------------
extern "C" void kernel_launch(void* const* d_in, const int* in_sizes, int n_in,
                              void* d_out, int out_size) {
    const float* x        = (const float*)d_in[0];
    const float* in_proj  = (const float*)d_in[1];
    const float* conv_w   = (const float*)d_in[2];
    const float* conv_b   = (const float*)d_in[3];
    const float* dt_bias  = (const float*)d_in[4];
    const float* A_log    = (const float*)d_in[5];
    const float* D_param  = (const float*)d_in[6];
    const float* norm_w   = (const float*)d_in[7];
    const float* out_proj = (const float*)d_in[8];
    const float* ln1_w    = (const float*)d_in[9];
    const float* ln1_b    = (const float*)d_in[10];
    const float* ln2_w    = (const float*)d_in[11];
    const float* ln2_b    = (const float*)d_in[12];
    const float* ff_w1    = (const float*)d_in[13];
    const float* ff_b1    = (const float*)d_in[14];
    const float* ff_w2    = (const float*)d_in[15];
    const float* ff_b2    = (const float*)d_in[16];
    float* out = (float*)d_out;

    float *p_zx, *p_xbcf, *p_xbcb, *p_dtp, *p_dAe, *p_yf, *p_yb, *p_mi;
    bf16 *p_xnh, *p_xnl, *p_ysh, *p_ysl, *p_mh, *p_ml, *p_h1h, *p_h1l;
    bf16 *p_wip_h, *p_wip_l, *p_wop_h, *p_wop_l, *p_w1_h, *p_w1_l, *p_w2_h, *p_w2_l;
    cudaGetSymbolAddress((void**)&p_zx,   g_zx);
    cudaGetSymbolAddress((void**)&p_xbcf, g_xbcf);
    cudaGetSymbolAddress((void**)&p_xbcb, g_xbcb);
    cudaGetSymbolAddress((void**)&p_dtp,  g_dtp);
    cudaGetSymbolAddress((void**)&p_dAe,  g_dAe);
    cudaGetSymbolAddress((void**)&p_yf,   g_yf);
    cudaGetSymbolAddress((void**)&p_yb,   g_yb);
    cudaGetSymbolAddress((void**)&p_mi,   g_mi);
    cudaGetSymbolAddress((void**)&p_xnh,  g_xnh);
    cudaGetSymbolAddress((void**)&p_xnl,  g_xnl);
    cudaGetSymbolAddress((void**)&p_ysh,  g_ysh);
    cudaGetSymbolAddress((void**)&p_ysl,  g_ysl);
    cudaGetSymbolAddress((void**)&p_mh,   g_mh);
    cudaGetSymbolAddress((void**)&p_ml,   g_ml);
    cudaGetSymbolAddress((void**)&p_h1h,  g_h1h);
    cudaGetSymbolAddress((void**)&p_h1l,  g_h1l);
    cudaGetSymbolAddress((void**)&p_wip_h, g_wip_h);
    cudaGetSymbolAddress((void**)&p_wip_l, g_wip_l);
    cudaGetSymbolAddress((void**)&p_wop_h, g_wop_h);
    cudaGetSymbolAddress((void**)&p_wop_l, g_wop_l);
    cudaGetSymbolAddress((void**)&p_w1_h,  g_w1_h);
    cudaGetSymbolAddress((void**)&p_w1_l,  g_w1_l);
    cudaGetSymbolAddress((void**)&p_w2_h,  g_w2_h);
    cudaGetSymbolAddress((void**)&p_w2_l,  g_w2_l);

    cudaFuncSetAttribute(gemm_bf16p<0,0>, cudaFuncAttributeMaxDynamicSharedMemorySize, GEMM_SMEM);
    cudaFuncSetAttribute(gemm_bf16p<1,1>, cudaFuncAttributeMaxDynamicSharedMemorySize, GEMM_SMEM);
    cudaFuncSetAttribute(gemm_bf16p<2,0>, cudaFuncAttributeMaxDynamicSharedMemorySize, GEMM_SMEM);

    // #0 split in_proj
    wsplit_kernel<<<(DIP*DMODEL/4 + 255) / 256, 256>>>(in_proj,  p_wip_h, p_wip_l, DIP*DMODEL/4);
    // #1 ln1(x) -> xn planes
    ln_hl_kernel<<<BT, 256>>>(x, ln1_w, ln1_b, p_xnh, p_xnl);
    // #2 split out_proj
    wsplit_kernel<<<(DMODEL*DINNER/4 + 255) / 256, 256>>>(out_proj, p_wop_h, p_wop_l, DMODEL*DINNER/4);
    // #3 zxbcdt = xn @ in_proj^T   [1024, 3224]   <-- ncu capture slot
    gemm_bf16p<0,0><<<dim3((DIP + 63) / 64, BT / 128), 256, GEMM_SMEM>>>(
        p_xnh, p_xnl, p_wip_h, p_wip_l, nullptr, nullptr, p_zx, nullptr, nullptr, BT, DIP, DMODEL);
    // #4 conv + silu (both directions)
    {
        long tot = (long)BT * CONVDIM;
        conv_kernel<<<(int)((tot + 255) / 256), 256>>>(p_zx, conv_w, conv_b, p_xbcf, p_xbcb);
    }
    // #5 dt processing
    dt_kernel<<<(BT * NHEADSn + 255) / 256, 256>>>(p_zx, dt_bias, A_log, p_dtp, p_dAe);
    // #6 SSM scan
    scan_kernel<<<2 * BSZn * NHEADSn, 256>>>(p_xbcf, p_xbcb, p_dtp, p_dAe, D_param, p_yf, p_yb);
    // #7 gate + RMSNorm per dir + sum -> ysum planes
    gatenorm_kernel<<<BT, 256>>>(p_yf, p_yb, p_zx, norm_w, p_ysh, p_ysl);
    // #8 mi = ysum @ out_proj^T  [1024, 768]
    gemm_bf16p<0,0><<<dim3(DMODEL / 64, BT / 128), 256, GEMM_SMEM>>>(
        p_ysh, p_ysl, p_wop_h, p_wop_l, nullptr, nullptr, p_mi, nullptr, nullptr, BT, DMODEL, DINNER);
    // #9 ln2 -> m planes
    ln_hl_kernel<<<BT, 256>>>(p_mi, ln2_w, ln2_b, p_mh, p_ml);
    // #10 split ff_w1
    wsplit_kernel<<<(DFF*DMODEL/4 + 255) / 256, 256>>>(ff_w1, p_w1_h, p_w1_l, DFF*DMODEL/4);
    // #11 h1 = gelu(m @ ff_w1^T + b1) -> h1 planes  [1024, 3072]
    gemm_bf16p<1,1><<<dim3(DFF / 64, BT / 128), 256, GEMM_SMEM>>>(
        p_mh, p_ml, p_w1_h, p_w1_l, ff_b1, nullptr, nullptr, p_h1h, p_h1l, BT, DFF, DMODEL);
    // #12 split ff_w2
    wsplit_kernel<<<(DMODEL*DFF/4 + 255) / 256, 256>>>(ff_w2, p_w2_h, p_w2_l, DMODEL*DFF/4);
    // #13 out = h1 @ ff_w2^T + b2 + x
    gemm_bf16p<2,0><<<dim3(DMODEL / 64, BT / 128), 256, GEMM_SMEM>>>(
        p_h1h, p_h1l, p_w2_h, p_w2_l, ff_b2, x, out, nullptr, nullptr, BT, DMODEL, DFF);
}

// round 9
// speedup vs baseline: 1.0940x; 1.0940x over previous
#include <cuda_runtime.h>
#include <cuda_bf16.h>
#include <math.h>
#include <stdint.h>

#define BSZn   2
#define SEQn   512
#define DMODEL 768
#define DINNER 1536
#define NHEADSn 24
#define HEADDIMn 64
#define DSTATEn 64
#define CONVDIM 1664
#define DIP    3224
#define BT     (BSZn*SEQn)   // 1024
#define DFF    3072
#define EPSV   1e-5f

typedef __nv_bfloat16 bf16;

// ---------------- scratch ----------------
__device__ float g_zx  [BT*DIP];
__device__ float g_dtpX[4];   // unused placeholder (kept for symbol stability)
__device__ float g_yf  [BT*DINNER];
__device__ float g_yb  [BT*DINNER];
__device__ float g_mi  [BT*DMODEL];
__device__ __align__(16) bf16 g_xnh [BT*DMODEL],  g_xnl [BT*DMODEL];
__device__ __align__(16) bf16 g_ysh [BT*DINNER],  g_ysl [BT*DINNER];
__device__ __align__(16) bf16 g_mh  [BT*DMODEL],  g_ml  [BT*DMODEL];
__device__ __align__(16) bf16 g_h1h [BT*DFF],     g_h1l [BT*DFF];
__device__ __align__(16) bf16 g_wip_h[DIP*DMODEL],   g_wip_l[DIP*DMODEL];
__device__ __align__(16) bf16 g_wop_h[DMODEL*DINNER], g_wop_l[DMODEL*DINNER];
__device__ __align__(16) bf16 g_w1_h [DFF*DMODEL],   g_w1_l [DFF*DMODEL];
__device__ __align__(16) bf16 g_w2_h [DMODEL*DFF],   g_w2_l [DMODEL*DFF];

// ---------------- helpers ----------------
__device__ __forceinline__ float warp_sum(float v) {
    #pragma unroll
    for (int o = 16; o > 0; o >>= 1) v += __shfl_xor_sync(0xffffffffu, v, o);
    return v;
}
__device__ __forceinline__ float siluf(float x) { return x / (1.f + expf(-x)); }
__device__ __forceinline__ float geluf(float x) { return 0.5f * x * (1.f + erff(x * 0.70710678118654752f)); }

__device__ __forceinline__ uint32_t smem_u32(const void* p) {
    uint32_t a;
    asm("{ .reg .u64 t; cvta.to.shared.u64 t, %1; cvt.u32.u64 %0, t; }" : "=r"(a) : "l"(p));
    return a;
}
__device__ __forceinline__ void mma_bf16(float* c, const uint32_t* a, const uint32_t* b) {
    asm volatile(
        "mma.sync.aligned.m16n8k16.row.col.f32.bf16.bf16.f32 "
        "{%0,%1,%2,%3},{%4,%5,%6,%7},{%8,%9},{%0,%1,%2,%3};"
        : "+f"(c[0]), "+f"(c[1]), "+f"(c[2]), "+f"(c[3])
        : "r"(a[0]), "r"(a[1]), "r"(a[2]), "r"(a[3]), "r"(b[0]), "r"(b[1]));
}
__device__ __forceinline__ void ldsm4(uint32_t* r, uint32_t addr) {
    asm volatile("ldmatrix.sync.aligned.m8n8.x4.shared.b16 {%0,%1,%2,%3}, [%4];"
                 : "=r"(r[0]), "=r"(r[1]), "=r"(r[2]), "=r"(r[3]) : "r"(addr));
}
__device__ __forceinline__ void cpasync16(uint32_t dst, const void* src, uint32_t ssz) {
    asm volatile("cp.async.cg.shared.global [%0], [%1], 16, %2;"
                 :: "r"(dst), "l"(src), "r"(ssz) : "memory");
}
__device__ __forceinline__ void cp_commit() {
    asm volatile("cp.async.commit_group;" ::: "memory");
}
template<int Np>
__device__ __forceinline__ void cp_wait() {
    asm volatile("cp.async.wait_group %0;" :: "n"(Np) : "memory");
}
__device__ __forceinline__ void split1(float x, bf16& h, bf16& l) {
    h = __float2bfloat16_rn(x);
    l = __float2bfloat16_rn(x - __bfloat162float(h));
}

// ---------------- weight hi/lo split ----------------
__global__ void wsplit_kernel(const float* __restrict__ w, bf16* __restrict__ wh,
                              bf16* __restrict__ wl, int n4) {
    int i = blockIdx.x * blockDim.x + threadIdx.x;
    if (i >= n4) return;
    float4 v = reinterpret_cast<const float4*>(w)[i];
    bf16 h0, h1, h2, h3, l0, l1, l2, l3;
    split1(v.x, h0, l0); split1(v.y, h1, l1);
    split1(v.z, h2, l2); split1(v.w, h3, l3);
    __nv_bfloat162 hp0; hp0.x = h0; hp0.y = h1;
    __nv_bfloat162 hp1; hp1.x = h2; hp1.y = h3;
    __nv_bfloat162 lp0; lp0.x = l0; lp0.y = l1;
    __nv_bfloat162 lp1; lp1.x = l2; lp1.y = l3;
    uint2 hh = make_uint2(*reinterpret_cast<uint32_t*>(&hp0), *reinterpret_cast<uint32_t*>(&hp1));
    uint2 ll = make_uint2(*reinterpret_cast<uint32_t*>(&lp0), *reinterpret_cast<uint32_t*>(&lp1));
    reinterpret_cast<uint2*>(wh)[i] = hh;
    reinterpret_cast<uint2*>(wl)[i] = ll;
}

// ---------------- LayerNorm -> bf16 hi/lo planes ----------------
__global__ void ln_hl_kernel(const float* __restrict__ in, const float* __restrict__ w,
                             const float* __restrict__ b,
                             bf16* __restrict__ oh, bf16* __restrict__ ol) {
    int row = blockIdx.x;
    int tid = threadIdx.x;
    const float* x = in + (long)row * DMODEL;
    float v[3], s = 0.f, ss = 0.f;
    #pragma unroll
    for (int i = 0; i < 3; i++) {
        v[i] = x[tid + i * 256];
        s += v[i]; ss += v[i] * v[i];
    }
    __shared__ float sr[8], sr2[8], bres[2];
    float ws = warp_sum(s), ws2 = warp_sum(ss);
    int lane = tid & 31, wid = tid >> 5;
    if (lane == 0) { sr[wid] = ws; sr2[wid] = ws2; }
    __syncthreads();
    if (tid == 0) {
        float a = 0.f, c = 0.f;
        #pragma unroll
        for (int i = 0; i < 8; i++) { a += sr[i]; c += sr2[i]; }
        bres[0] = a; bres[1] = c;
    }
    __syncthreads();
    float mu  = bres[0] * (1.f / DMODEL);
    float var = bres[1] * (1.f / DMODEL) - mu * mu;
    float r = rsqrtf(var + EPSV);
    #pragma unroll
    for (int i = 0; i < 3; i++) {
        int c = tid + i * 256;
        float o = (v[i] - mu) * r * w[c] + b[c];
        bf16 h, l; split1(o, h, l);
        oh[(long)row * DMODEL + c] = h;
        ol[(long)row * DMODEL + c] = l;
    }
}

// ======= GEMM (pre-split bf16 hi/lo, cp.async x3, ldmatrix, HMMA 3-product) ==
#define RS 80
#define A_PL (128 * RS)
#define B_PL (64 * RS)
#define STG  (2 * A_PL + 2 * B_PL)
#define GEMM_SMEM (3 * STG)

template<int EPI, int OUTHL>
__global__ void __launch_bounds__(256, 2) gemm_bf16p(
        const bf16* __restrict__ Ah_, const bf16* __restrict__ Al_,
        const bf16* __restrict__ Wh_, const bf16* __restrict__ Wl_,
        const float* __restrict__ bias, const float* __restrict__ resid,
        float* __restrict__ C, bf16* __restrict__ Ch, bf16* __restrict__ Cl,
        int M, int N, int K) {
    extern __shared__ char smem[];
    uint32_t sb = smem_u32(smem);
    const int tid = threadIdx.x;
    const int lane = tid & 31, wid = tid >> 5;
    const int warpM = wid & 3, warpN = wid >> 2;
    const int row0 = blockIdx.y * 128;
    const int col0 = blockIdx.x * 64;
    const int quad = lane >> 3, r8 = lane & 7;
    const int g = lane >> 2, tg = lane & 3;

    float acc[2][4][4];
    #pragma unroll
    for (int mt = 0; mt < 2; mt++)
        #pragma unroll
        for (int nt = 0; nt < 4; nt++)
            #pragma unroll
            for (int i = 0; i < 4; i++) acc[mt][nt][i] = 0.f;

    const int ar0 = tid >> 2,          ac0 = tid & 3;
    const int ar1 = (tid + 256) >> 2,  ac1 = ac0;
    const int br  = tid >> 2,          bc  = tid & 3;
    const int bn  = col0 + br;
    const int bnc = bn < N ? bn : (N - 1);
    const uint32_t bsz = bn < N ? 16u : 0u;

    auto issue = [&](int kt, int st) {
        uint32_t base = sb + st * STG;
        int k0 = kt * 32;
        cpasync16(base + ar0 * RS + ac0 * 16,        &Ah_[(long)(row0 + ar0) * K + k0 + ac0 * 8], 16);
        cpasync16(base + A_PL + ar0 * RS + ac0 * 16, &Al_[(long)(row0 + ar0) * K + k0 + ac0 * 8], 16);
        cpasync16(base + ar1 * RS + ac1 * 16,        &Ah_[(long)(row0 + ar1) * K + k0 + ac1 * 8], 16);
        cpasync16(base + A_PL + ar1 * RS + ac1 * 16, &Al_[(long)(row0 + ar1) * K + k0 + ac1 * 8], 16);
        cpasync16(base + 2 * A_PL + br * RS + bc * 16,        &Wh_[(long)bnc * K + k0 + bc * 8], bsz);
        cpasync16(base + 2 * A_PL + B_PL + br * RS + bc * 16, &Wl_[(long)bnc * K + k0 + bc * 8], bsz);
        cp_commit();
    };

    const int ntiles = K / 32;
    issue(0, 0);
    issue(1, 1);

    for (int kt = 0; kt < ntiles; kt++) {
        cp_wait<1>();
        __syncthreads();
        if (kt + 2 < ntiles) issue(kt + 2, (kt + 2) % 3);
        else cp_commit();

        uint32_t base = sb + (kt % 3) * STG;
        uint32_t pAh = base, pAl = base + A_PL;
        uint32_t pBh = base + 2 * A_PL, pBl = pBh + B_PL;

        // double-buffered fragments across the 2 k-slabs for ILP
        uint32_t ah[2][2][4], al[2][2][4], bh[2][2][4], bl[2][2][4];
        {
            const int slab = 0;
            uint32_t kbA = slab * 32 + (quad >> 1) * 16;
            uint32_t kbB = slab * 32 + (quad & 1) * 16;
            #pragma unroll
            for (int mt = 0; mt < 2; mt++) {
                uint32_t ra = (uint32_t)((warpM * 32 + mt * 16 + (quad & 1) * 8 + r8) * RS) + kbA;
                ldsm4(ah[0][mt], pAh + ra);
                ldsm4(al[0][mt], pAl + ra);
            }
            #pragma unroll
            for (int nt = 0; nt < 2; nt++) {
                uint32_t rb = (uint32_t)((warpN * 32 + nt * 16 + (quad >> 1) * 8 + r8) * RS) + kbB;
                ldsm4(bh[0][nt], pBh + rb);
                ldsm4(bl[0][nt], pBl + rb);
            }
        }
        #pragma unroll
        for (int slab = 0; slab < 2; slab++) {
            if (slab == 0) {
                uint32_t kbA = 32 + (quad >> 1) * 16;
                uint32_t kbB = 32 + (quad & 1) * 16;
                #pragma unroll
                for (int mt = 0; mt < 2; mt++) {
                    uint32_t ra = (uint32_t)((warpM * 32 + mt * 16 + (quad & 1) * 8 + r8) * RS) + kbA;
                    ldsm4(ah[1][mt], pAh + ra);
                    ldsm4(al[1][mt], pAl + ra);
                }
                #pragma unroll
                for (int nt = 0; nt < 2; nt++) {
                    uint32_t rb = (uint32_t)((warpN * 32 + nt * 16 + (quad >> 1) * 8 + r8) * RS) + kbB;
                    ldsm4(bh[1][nt], pBh + rb);
                    ldsm4(bl[1][nt], pBl + rb);
                }
            }
            #pragma unroll
            for (int mt = 0; mt < 2; mt++)
                #pragma unroll
                for (int nt16 = 0; nt16 < 2; nt16++) {
                    mma_bf16(acc[mt][nt16 * 2 + 0], ah[slab][mt], &bl[slab][nt16][0]);
                    mma_bf16(acc[mt][nt16 * 2 + 0], al[slab][mt], &bh[slab][nt16][0]);
                    mma_bf16(acc[mt][nt16 * 2 + 0], ah[slab][mt], &bh[slab][nt16][0]);
                    mma_bf16(acc[mt][nt16 * 2 + 1], ah[slab][mt], &bl[slab][nt16][2]);
                    mma_bf16(acc[mt][nt16 * 2 + 1], al[slab][mt], &bh[slab][nt16][2]);
                    mma_bf16(acc[mt][nt16 * 2 + 1], ah[slab][mt], &bh[slab][nt16][2]);
                }
        }
    }

    #pragma unroll
    for (int mt = 0; mt < 2; mt++) {
        int rbase = row0 + warpM * 32 + mt * 16 + g;
        #pragma unroll
        for (int nt = 0; nt < 4; nt++) {
            int col = col0 + warpN * 32 + nt * 8 + tg * 2;
            if (col < N) {
                float2 v0 = make_float2(acc[mt][nt][0], acc[mt][nt][1]);
                float2 v1 = make_float2(acc[mt][nt][2], acc[mt][nt][3]);
                if (EPI == 1) {
                    float b0 = bias[col], b1 = bias[col + 1];
                    v0.x = geluf(v0.x + b0); v0.y = geluf(v0.y + b1);
                    v1.x = geluf(v1.x + b0); v1.y = geluf(v1.y + b1);
                }
                if (EPI == 2) {
                    float b0 = bias[col], b1 = bias[col + 1];
                    float2 r0 = *reinterpret_cast<const float2*>(&resid[(long)rbase * N + col]);
                    float2 r1 = *reinterpret_cast<const float2*>(&resid[(long)(rbase + 8) * N + col]);
                    v0.x += b0 + r0.x; v0.y += b1 + r0.y;
                    v1.x += b0 + r1.x; v1.y += b1 + r1.y;
                }
                if (OUTHL) {
                    bf16 h0, h1, l0, l1;
                    split1(v0.x, h0, l0); split1(v0.y, h1, l1);
                    __nv_bfloat162 hp; hp.x = h0; hp.y = h1;
                    __nv_bfloat162 lp; lp.x = l0; lp.y = l1;
                    *reinterpret_cast<uint32_t*>(&Ch[(long)rbase * N + col]) = *reinterpret_cast<uint32_t*>(&hp);
                    *reinterpret_cast<uint32_t*>(&Cl[(long)rbase * N + col]) = *reinterpret_cast<uint32_t*>(&lp);
                    split1(v1.x, h0, l0); split1(v1.y, h1, l1);
                    hp.x = h0; hp.y = h1; lp.x = l0; lp.y = l1;
                    *reinterpret_cast<uint32_t*>(&Ch[(long)(rbase + 8) * N + col]) = *reinterpret_cast<uint32_t*>(&hp);
                    *reinterpret_cast<uint32_t*>(&Cl[(long)(rbase + 8) * N + col]) = *reinterpret_cast<uint32_t*>(&lp);
                } else {
                    *reinterpret_cast<float2*>(&C[(long)rbase * N + col])       = v0;
                    *reinterpret_cast<float2*>(&C[(long)(rbase + 8) * N + col]) = v1;
                }
            }
        }
    }
}

// ===== fused conv + dt + SSM scan =====
// 96 blocks (dir,b,head) x 256 thr. Producers (tid<192) convolve raw zx rows
// (4-tap sliding window in regs, silu) into double-buffered smem; tid 192/196
// produce dt/dA. All threads consume: thread (p=tid>>2,q=tid&3) owns states
// n = 4j+q. 2 steps per barrier; raw loads pipelined 3 iterations (6 steps) ahead.
__global__ void __launch_bounds__(256) scan_fused(
        const float* __restrict__ zx, const float* __restrict__ cw,
        const float* __restrict__ cb, const float* __restrict__ dt_bias,
        const float* __restrict__ A_log, const float* __restrict__ Dp_,
        float* __restrict__ yf, float* __restrict__ yb) {
    int blk = blockIdx.x;
    int dir = blk / (BSZn * NHEADSn);
    int rem = blk % (BSZn * NHEADSn);
    int b = rem / NHEADSn, hh = rem % NHEADSn;
    float* y = dir ? yb : yf;
    int tid = threadIdx.x;
    int p = tid >> 2, q = tid & 3;

    __shared__ float sX[2][2][64], sB[2][2][64], sC[2][2][64];
    __shared__ float sdt[2][2], sdA[2][2];

    int lch = tid & 63;
    int role = tid >> 6;               // 0=B,1=C,2=x,3=aux
    bool isProd = role < 3;
    int convc = (role == 0) ? (DINNER + lch)
              : (role == 1) ? (DINNER + DSTATEn + lch)
              : (hh * HEADDIMn + lch);
    int zcol  = DINNER + convc;        // column within zx row
    float w0 = 0.f, w1 = 0.f, w2 = 0.f, w3 = 0.f, cbv = 0.f;
    if (isProd) {
        w0 = cw[convc * 4 + 0]; w1 = cw[convc * 4 + 1];
        w2 = cw[convc * 4 + 2]; w3 = cw[convc * 4 + 3];
        cbv = cb[convc];
    }
    bool isDt = (tid == 192) || (tid == 196);
    int dtpar = (tid == 196) ? 1 : 0;
    int dtcol = DINNER + CONVDIM + hh;
    float eA = expf(A_log[hh]);
    float dtb = dt_bias[hh];
    float Dv = Dp_[hh];
    long rowbase = (long)b * SEQn;

    auto ldraw = [&](int k, int col) -> float {
        if (k < 0 || k >= SEQn) return 0.f;
        int t = dir ? (SEQn - 1 - k) : k;
        return zx[(rowbase + t) * DIP + col];
    };

    // producer pipeline state
    float rr0 = 0.f, rr1 = 0.f, rr2 = 0.f;           // R(s-3..s-1) for next step
    float pA0 = 0.f, pA1 = 0.f, pB0 = 0.f, pB1 = 0.f, pC0 = 0.f, pC1 = 0.f;
    float dpA = 0.f, dpB = 0.f, dpC = 0.f;

    // prologue: produce steps 0,1 into iterbuf 0
    if (isProd) {
        float n0 = ldraw(0, zcol), n1 = ldraw(1, zcol);
        pA0 = ldraw(2, zcol); pA1 = ldraw(3, zcol);
        pB0 = ldraw(4, zcol); pB1 = ldraw(5, zcol);
        pC0 = ldraw(6, zcol); pC1 = ldraw(7, zcol);
        float* dst = (role == 0) ? &sB[0][0][lch] : (role == 1) ? &sC[0][0][lch] : &sX[0][0][lch];
        float cv0 = cbv + w3 * n0;
        dst[0] = siluf(cv0);
        float cv1 = cbv + w2 * n0 + w3 * n1;
        dst[64] = siluf(cv1);
        rr0 = 0.f; rr1 = n0; rr2 = n1;
    }
    if (isDt) {
        float d0 = ldraw(dtpar, dtcol);
        dpA = ldraw(dtpar + 2, dtcol);
        dpB = ldraw(dtpar + 4, dtcol);
        dpC = ldraw(dtpar + 6, dtcol);
        float d = d0 + dtb;
        float sp = (d > 20.f) ? d : log1pf(expf(d));
        sdt[0][dtpar] = sp;
        sdA[0][dtpar] = expf(-eA * sp);
    }

    float hst[16];
    #pragma unroll
    for (int j = 0; j < 16; j++) hst[j] = 0.f;

    for (int i = 0; i < SEQn / 2; i++) {
        __syncthreads();
        int ib = i & 1, nib = ib ^ 1;
        // ---- producers: steps 2i+2, 2i+3 into buf nib ----
        if (isProd) {
            int s0 = 2 * i + 2;
            if (s0 < SEQn) {
                float* dst = (role == 0) ? &sB[nib][0][lch] : (role == 1) ? &sC[nib][0][lch] : &sX[nib][0][lch];
                float cv0 = cbv + w0 * rr0 + w1 * rr1 + w2 * rr2 + w3 * pA0;
                dst[0] = siluf(cv0);
                float cv1 = cbv + w0 * rr1 + w1 * rr2 + w2 * pA0 + w3 * pA1;
                dst[64] = siluf(cv1);
                rr0 = rr2; rr1 = pA0; rr2 = pA1;
            }
            pA0 = pB0; pA1 = pB1; pB0 = pC0; pB1 = pC1;
            pC0 = ldraw(2 * i + 8, zcol); pC1 = ldraw(2 * i + 9, zcol);
        }
        if (isDt) {
            int s = 2 * i + 2 + dtpar;
            if (s < SEQn) {
                float d = dpA + dtb;
                float sp = (d > 20.f) ? d : log1pf(expf(d));
                sdt[nib][dtpar] = sp;
                sdA[nib][dtpar] = expf(-eA * sp);
            }
            dpA = dpB; dpB = dpC;
            dpC = ldraw(2 * i + 8 + dtpar, dtcol);
        }
        // ---- consumers: steps 2i, 2i+1 from buf ib ----
        #pragma unroll
        for (int sp_ = 0; sp_ < 2; sp_++) {
            int s = 2 * i + sp_;
            float cdt = sdt[ib][sp_], cdA = sdA[ib][sp_];
            float cx = sX[ib][sp_][p];
            float c1 = cdt * cx;
            float yv0 = (q == 0) ? Dv * cx : 0.f;
            float yv1 = 0.f, yv2 = 0.f, yv3 = 0.f;
            #pragma unroll
            for (int j = 0; j < 16; j += 4) {
                int n0 = 4 * j + q;
                hst[j]     = cdA * hst[j]     + c1 * sB[ib][sp_][n0];      yv0 += hst[j]     * sC[ib][sp_][n0];
                hst[j + 1] = cdA * hst[j + 1] + c1 * sB[ib][sp_][n0 + 4];  yv1 += hst[j + 1] * sC[ib][sp_][n0 + 4];
                hst[j + 2] = cdA * hst[j + 2] + c1 * sB[ib][sp_][n0 + 8];  yv2 += hst[j + 2] * sC[ib][sp_][n0 + 8];
                hst[j + 3] = cdA * hst[j + 3] + c1 * sB[ib][sp_][n0 + 12]; yv3 += hst[j + 3] * sC[ib][sp_][n0 + 12];
            }
            float yv = (yv0 + yv1) + (yv2 + yv3);
            yv += __shfl_xor_sync(0xffffffffu, yv, 1);
            yv += __shfl_xor_sync(0xffffffffu, yv, 2);
            if (q == 0) {
                int t = dir ? (SEQn - 1 - s) : s;
                y[(rowbase + t) * DINNER + hh * HEADDIMn + p] = yv;
            }
        }
    }
}

// ------ gate + RMSNorm + sum -> bf16 hi/lo planes ----------------
__global__ void gatenorm_kernel(const float* __restrict__ yf, const float* __restrict__ yb,
                                const float* __restrict__ zx, const float* __restrict__ nw,
                                bf16* __restrict__ oh, bf16* __restrict__ ol) {
    int row = blockIdx.x;
    int tid = threadIdx.x;
    const float* z = zx + (long)row * DIP;
    float gf[6], gb[6], ssf = 0.f, ssb = 0.f;
    #pragma unroll
    for (int i = 0; i < 6; i++) {
        int c = tid + i * 256;
        float s = siluf(z[c]);
        float a = yf[(long)row * DINNER + c] * s;
        float d = yb[(long)row * DINNER + c] * s;
        gf[i] = a; gb[i] = d;
        ssf += a * a; ssb += d * d;
    }
    __shared__ float r1[8], r2[8], bres[2];
    float w1 = warp_sum(ssf), w2 = warp_sum(ssb);
    int lane = tid & 31, wid = tid >> 5;
    if (lane == 0) { r1[wid] = w1; r2[wid] = w2; }
    __syncthreads();
    if (tid == 0) {
        float a = 0.f, c = 0.f;
        #pragma unroll
        for (int i = 0; i < 8; i++) { a += r1[i]; c += r2[i]; }
        bres[0] = a; bres[1] = c;
    }
    __syncthreads();
    float rf = rsqrtf(bres[0] * (1.f / DINNER) + EPSV);
    float rb = rsqrtf(bres[1] * (1.f / DINNER) + EPSV);
    #pragma unroll
    for (int i = 0; i < 6; i++) {
        int c = tid + i * 256;
        float o = (gf[i] * rf + gb[i] * rb) * nw[c];
        bf16 h, l; split1(o, h, l);
        oh[(long)row * DINNER + c] = h;
        ol[(long)row * DINNER + c] = l;
    }
}

// ---------------- launch ----------------
extern "C" void kernel_launch(void* const* d_in, const int* in_sizes, int n_in,
                              void* d_out, int out_size) {
    const float* x        = (const float*)d_in[0];
    const float* in_proj  = (const float*)d_in[1];
    const float* conv_w   = (const float*)d_in[2];
    const float* conv_b   = (const float*)d_in[3];
    const float* dt_bias  = (const float*)d_in[4];
    const float* A_log    = (const float*)d_in[5];
    const float* D_param  = (const float*)d_in[6];
    const float* norm_w   = (const float*)d_in[7];
    const float* out_proj = (const float*)d_in[8];
    const float* ln1_w    = (const float*)d_in[9];
    const float* ln1_b    = (const float*)d_in[10];
    const float* ln2_w    = (const float*)d_in[11];
    const float* ln2_b    = (const float*)d_in[12];
    const float* ff_w1    = (const float*)d_in[13];
    const float* ff_b1    = (const float*)d_in[14];
    const float* ff_w2    = (const float*)d_in[15];
    const float* ff_b2    = (const float*)d_in[16];
    float* out = (float*)d_out;

    float *p_zx, *p_yf, *p_yb, *p_mi;
    bf16 *p_xnh, *p_xnl, *p_ysh, *p_ysl, *p_mh, *p_ml, *p_h1h, *p_h1l;
    bf16 *p_wip_h, *p_wip_l, *p_wop_h, *p_wop_l, *p_w1_h, *p_w1_l, *p_w2_h, *p_w2_l;
    cudaGetSymbolAddress((void**)&p_zx,   g_zx);
    cudaGetSymbolAddress((void**)&p_yf,   g_yf);
    cudaGetSymbolAddress((void**)&p_yb,   g_yb);
    cudaGetSymbolAddress((void**)&p_mi,   g_mi);
    cudaGetSymbolAddress((void**)&p_xnh,  g_xnh);
    cudaGetSymbolAddress((void**)&p_xnl,  g_xnl);
    cudaGetSymbolAddress((void**)&p_ysh,  g_ysh);
    cudaGetSymbolAddress((void**)&p_ysl,  g_ysl);
    cudaGetSymbolAddress((void**)&p_mh,   g_mh);
    cudaGetSymbolAddress((void**)&p_ml,   g_ml);
    cudaGetSymbolAddress((void**)&p_h1h,  g_h1h);
    cudaGetSymbolAddress((void**)&p_h1l,  g_h1l);
    cudaGetSymbolAddress((void**)&p_wip_h, g_wip_h);
    cudaGetSymbolAddress((void**)&p_wip_l, g_wip_l);
    cudaGetSymbolAddress((void**)&p_wop_h, g_wop_h);
    cudaGetSymbolAddress((void**)&p_wop_l, g_wop_l);
    cudaGetSymbolAddress((void**)&p_w1_h,  g_w1_h);
    cudaGetSymbolAddress((void**)&p_w1_l,  g_w1_l);
    cudaGetSymbolAddress((void**)&p_w2_h,  g_w2_h);
    cudaGetSymbolAddress((void**)&p_w2_l,  g_w2_l);

    cudaFuncSetAttribute(gemm_bf16p<0,0>, cudaFuncAttributeMaxDynamicSharedMemorySize, GEMM_SMEM);
    cudaFuncSetAttribute(gemm_bf16p<1,1>, cudaFuncAttributeMaxDynamicSharedMemorySize, GEMM_SMEM);
    cudaFuncSetAttribute(gemm_bf16p<2,0>, cudaFuncAttributeMaxDynamicSharedMemorySize, GEMM_SMEM);

    // #0 ln1(x) -> xn planes
    ln_hl_kernel<<<BT, 256>>>(x, ln1_w, ln1_b, p_xnh, p_xnl);
    // #1 split in_proj
    wsplit_kernel<<<(DIP*DMODEL/4 + 255) / 256, 256>>>(in_proj,  p_wip_h, p_wip_l, DIP*DMODEL/4);
    // #2 zxbcdt = xn @ in_proj^T   [1024, 3224]
    gemm_bf16p<0,0><<<dim3((DIP + 63) / 64, BT / 128), 256, GEMM_SMEM>>>(
        p_xnh, p_xnl, p_wip_h, p_wip_l, nullptr, nullptr, p_zx, nullptr, nullptr, BT, DIP, DMODEL);
    // #3 fused conv + dt + SSM scan   <-- ncu capture slot
    scan_fused<<<2 * BSZn * NHEADSn, 256>>>(p_zx, conv_w, conv_b, dt_bias, A_log, D_param, p_yf, p_yb);
    // #4 gate + RMSNorm per dir + sum -> ysum planes
    gatenorm_kernel<<<BT, 256>>>(p_yf, p_yb, p_zx, norm_w, p_ysh, p_ysl);
    // #5 split out_proj
    wsplit_kernel<<<(DMODEL*DINNER/4 + 255) / 256, 256>>>(out_proj, p_wop_h, p_wop_l, DMODEL*DINNER/4);
    // #6 mi = ysum @ out_proj^T  [1024, 768]
    gemm_bf16p<0,0><<<dim3(DMODEL / 64, BT / 128), 256, GEMM_SMEM>>>(
        p_ysh, p_ysl, p_wop_h, p_wop_l, nullptr, nullptr, p_mi, nullptr, nullptr, BT, DMODEL, DINNER);
    // #7 ln2 -> m planes
    ln_hl_kernel<<<BT, 256>>>(p_mi, ln2_w, ln2_b, p_mh, p_ml);
    // #8 split ff_w1
    wsplit_kernel<<<(DFF*DMODEL/4 + 255) / 256, 256>>>(ff_w1, p_w1_h, p_w1_l, DFF*DMODEL/4);
    // #9 h1 = gelu(m @ ff_w1^T + b1) -> h1 planes  [1024, 3072]
    gemm_bf16p<1,1><<<dim3(DFF / 64, BT / 128), 256, GEMM_SMEM>>>(
        p_mh, p_ml, p_w1_h, p_w1_l, ff_b1, nullptr, nullptr, p_h1h, p_h1l, BT, DFF, DMODEL);
    // #10 split ff_w2
    wsplit_kernel<<<(DMODEL*DFF/4 + 255) / 256, 256>>>(ff_w2, p_w2_h, p_w2_l, DMODEL*DFF/4);
    // #11 out = h1 @ ff_w2^T + b2 + x
    gemm_bf16p<2,0><<<dim3(DMODEL / 64, BT / 128), 256, GEMM_SMEM>>>(
        p_h1h, p_h1l, p_w2_h, p_w2_l, ff_b2, x, out, nullptr, nullptr, BT, DMODEL, DFF);
}

// round 10
// speedup vs baseline: 1.1893x; 1.0871x over previous
#include <cuda_runtime.h>
#include <cuda_bf16.h>
#include <math.h>
#include <stdint.h>

#define BSZn   2
#define SEQn   512
#define DMODEL 768
#define DINNER 1536
#define NHEADSn 24
#define HEADDIMn 64
#define DSTATEn 64
#define CONVDIM 1664
#define DIP    3224
#define BT     (BSZn*SEQn)   // 1024
#define DFF    3072
#define EPSV   1e-5f

typedef __nv_bfloat16 bf16;

// ---------------- scratch ----------------
__device__ float g_zx  [BT*DIP];
__device__ float g_yf  [BT*DINNER];
__device__ float g_yb  [BT*DINNER];
__device__ float g_mi  [BT*DMODEL];
__device__ __align__(16) bf16 g_xnh [BT*DMODEL],  g_xnl [BT*DMODEL];
__device__ __align__(16) bf16 g_ysh [BT*DINNER],  g_ysl [BT*DINNER];
__device__ __align__(16) bf16 g_mh  [BT*DMODEL],  g_ml  [BT*DMODEL];
__device__ __align__(16) bf16 g_h1h [BT*DFF],     g_h1l [BT*DFF];
__device__ __align__(16) bf16 g_wip_h[DIP*DMODEL],   g_wip_l[DIP*DMODEL];
__device__ __align__(16) bf16 g_wop_h[DMODEL*DINNER], g_wop_l[DMODEL*DINNER];
__device__ __align__(16) bf16 g_w1_h [DFF*DMODEL],   g_w1_l [DFF*DMODEL];
__device__ __align__(16) bf16 g_w2_h [DMODEL*DFF],   g_w2_l [DMODEL*DFF];

// ---------------- helpers ----------------
__device__ __forceinline__ float warp_sum(float v) {
    #pragma unroll
    for (int o = 16; o > 0; o >>= 1) v += __shfl_xor_sync(0xffffffffu, v, o);
    return v;
}
__device__ __forceinline__ float siluf(float x) { return x / (1.f + expf(-x)); }
__device__ __forceinline__ float geluf(float x) { return 0.5f * x * (1.f + erff(x * 0.70710678118654752f)); }

__device__ __forceinline__ uint32_t smem_u32(const void* p) {
    uint32_t a;
    asm("{ .reg .u64 t; cvta.to.shared.u64 t, %1; cvt.u32.u64 %0, t; }" : "=r"(a) : "l"(p));
    return a;
}
__device__ __forceinline__ void mma_bf16(float* c, const uint32_t* a, const uint32_t* b) {
    asm volatile(
        "mma.sync.aligned.m16n8k16.row.col.f32.bf16.bf16.f32 "
        "{%0,%1,%2,%3},{%4,%5,%6,%7},{%8,%9},{%0,%1,%2,%3};"
        : "+f"(c[0]), "+f"(c[1]), "+f"(c[2]), "+f"(c[3])
        : "r"(a[0]), "r"(a[1]), "r"(a[2]), "r"(a[3]), "r"(b[0]), "r"(b[1]));
}
__device__ __forceinline__ void ldsm4(uint32_t* r, uint32_t addr) {
    asm volatile("ldmatrix.sync.aligned.m8n8.x4.shared.b16 {%0,%1,%2,%3}, [%4];"
                 : "=r"(r[0]), "=r"(r[1]), "=r"(r[2]), "=r"(r[3]) : "r"(addr));
}
__device__ __forceinline__ void cpasync16(uint32_t dst, const void* src, uint32_t ssz) {
    asm volatile("cp.async.cg.shared.global [%0], [%1], 16, %2;"
                 :: "r"(dst), "l"(src), "r"(ssz) : "memory");
}
__device__ __forceinline__ void cp_commit() {
    asm volatile("cp.async.commit_group;" ::: "memory");
}
template<int Np>
__device__ __forceinline__ void cp_wait() {
    asm volatile("cp.async.wait_group %0;" :: "n"(Np) : "memory");
}
__device__ __forceinline__ void split1(float x, bf16& h, bf16& l) {
    h = __float2bfloat16_rn(x);
    l = __float2bfloat16_rn(x - __bfloat162float(h));
}

// ---------------- weight hi/lo split ----------------
__global__ void wsplit_kernel(const float* __restrict__ w, bf16* __restrict__ wh,
                              bf16* __restrict__ wl, int n4) {
    int i = blockIdx.x * blockDim.x + threadIdx.x;
    if (i >= n4) return;
    float4 v = reinterpret_cast<const float4*>(w)[i];
    bf16 h0, h1, h2, h3, l0, l1, l2, l3;
    split1(v.x, h0, l0); split1(v.y, h1, l1);
    split1(v.z, h2, l2); split1(v.w, h3, l3);
    __nv_bfloat162 hp0; hp0.x = h0; hp0.y = h1;
    __nv_bfloat162 hp1; hp1.x = h2; hp1.y = h3;
    __nv_bfloat162 lp0; lp0.x = l0; lp0.y = l1;
    __nv_bfloat162 lp1; lp1.x = l2; lp1.y = l3;
    uint2 hh = make_uint2(*reinterpret_cast<uint32_t*>(&hp0), *reinterpret_cast<uint32_t*>(&hp1));
    uint2 ll = make_uint2(*reinterpret_cast<uint32_t*>(&lp0), *reinterpret_cast<uint32_t*>(&lp1));
    reinterpret_cast<uint2*>(wh)[i] = hh;
    reinterpret_cast<uint2*>(wl)[i] = ll;
}

// ---------------- LayerNorm -> bf16 hi/lo planes ----------------
__global__ void ln_hl_kernel(const float* __restrict__ in, const float* __restrict__ w,
                             const float* __restrict__ b,
                             bf16* __restrict__ oh, bf16* __restrict__ ol) {
    int row = blockIdx.x;
    int tid = threadIdx.x;
    const float* x = in + (long)row * DMODEL;
    float v[3], s = 0.f, ss = 0.f;
    #pragma unroll
    for (int i = 0; i < 3; i++) {
        v[i] = x[tid + i * 256];
        s += v[i]; ss += v[i] * v[i];
    }
    __shared__ float sr[8], sr2[8], bres[2];
    float ws = warp_sum(s), ws2 = warp_sum(ss);
    int lane = tid & 31, wid = tid >> 5;
    if (lane == 0) { sr[wid] = ws; sr2[wid] = ws2; }
    __syncthreads();
    if (tid == 0) {
        float a = 0.f, c = 0.f;
        #pragma unroll
        for (int i = 0; i < 8; i++) { a += sr[i]; c += sr2[i]; }
        bres[0] = a; bres[1] = c;
    }
    __syncthreads();
    float mu  = bres[0] * (1.f / DMODEL);
    float var = bres[1] * (1.f / DMODEL) - mu * mu;
    float r = rsqrtf(var + EPSV);
    #pragma unroll
    for (int i = 0; i < 3; i++) {
        int c = tid + i * 256;
        float o = (v[i] - mu) * r * w[c] + b[c];
        bf16 h, l; split1(o, h, l);
        oh[(long)row * DMODEL + c] = h;
        ol[(long)row * DMODEL + c] = l;
    }
}

// ======= GEMM (pre-split bf16 hi/lo, cp.async x3, ldmatrix, HMMA 3-product) ==
#define RS 80
#define A_PL (128 * RS)
#define B_PL (64 * RS)
#define STG  (2 * A_PL + 2 * B_PL)
#define GEMM_SMEM (3 * STG)

template<int EPI, int OUTHL>
__global__ void __launch_bounds__(256, 2) gemm_bf16p(
        const bf16* __restrict__ Ah_, const bf16* __restrict__ Al_,
        const bf16* __restrict__ Wh_, const bf16* __restrict__ Wl_,
        const float* __restrict__ bias, const float* __restrict__ resid,
        float* __restrict__ C, bf16* __restrict__ Ch, bf16* __restrict__ Cl,
        int M, int N, int K) {
    extern __shared__ char smem[];
    uint32_t sb = smem_u32(smem);
    const int tid = threadIdx.x;
    const int lane = tid & 31, wid = tid >> 5;
    const int warpM = wid & 3, warpN = wid >> 2;
    const int row0 = blockIdx.y * 128;
    const int col0 = blockIdx.x * 64;
    const int quad = lane >> 3, r8 = lane & 7;
    const int g = lane >> 2, tg = lane & 3;

    float acc[2][4][4];
    #pragma unroll
    for (int mt = 0; mt < 2; mt++)
        #pragma unroll
        for (int nt = 0; nt < 4; nt++)
            #pragma unroll
            for (int i = 0; i < 4; i++) acc[mt][nt][i] = 0.f;

    const int ar0 = tid >> 2,          ac0 = tid & 3;
    const int ar1 = (tid + 256) >> 2,  ac1 = ac0;
    const int br  = tid >> 2,          bc  = tid & 3;
    const int bn  = col0 + br;
    const int bnc = bn < N ? bn : (N - 1);
    const uint32_t bsz = bn < N ? 16u : 0u;

    auto issue = [&](int kt, int st) {
        uint32_t base = sb + st * STG;
        int k0 = kt * 32;
        cpasync16(base + ar0 * RS + ac0 * 16,        &Ah_[(long)(row0 + ar0) * K + k0 + ac0 * 8], 16);
        cpasync16(base + A_PL + ar0 * RS + ac0 * 16, &Al_[(long)(row0 + ar0) * K + k0 + ac0 * 8], 16);
        cpasync16(base + ar1 * RS + ac1 * 16,        &Ah_[(long)(row0 + ar1) * K + k0 + ac1 * 8], 16);
        cpasync16(base + A_PL + ar1 * RS + ac1 * 16, &Al_[(long)(row0 + ar1) * K + k0 + ac1 * 8], 16);
        cpasync16(base + 2 * A_PL + br * RS + bc * 16,        &Wh_[(long)bnc * K + k0 + bc * 8], bsz);
        cpasync16(base + 2 * A_PL + B_PL + br * RS + bc * 16, &Wl_[(long)bnc * K + k0 + bc * 8], bsz);
        cp_commit();
    };

    const int ntiles = K / 32;
    issue(0, 0);
    issue(1, 1);

    for (int kt = 0; kt < ntiles; kt++) {
        cp_wait<1>();
        __syncthreads();
        if (kt + 2 < ntiles) issue(kt + 2, (kt + 2) % 3);
        else cp_commit();

        uint32_t base = sb + (kt % 3) * STG;
        uint32_t pAh = base, pAl = base + A_PL;
        uint32_t pBh = base + 2 * A_PL, pBl = pBh + B_PL;

        uint32_t ah[2][2][4], al[2][2][4], bh[2][2][4], bl[2][2][4];
        {
            uint32_t kbA = (quad >> 1) * 16;
            uint32_t kbB = (quad & 1) * 16;
            #pragma unroll
            for (int mt = 0; mt < 2; mt++) {
                uint32_t ra = (uint32_t)((warpM * 32 + mt * 16 + (quad & 1) * 8 + r8) * RS) + kbA;
                ldsm4(ah[0][mt], pAh + ra);
                ldsm4(al[0][mt], pAl + ra);
            }
            #pragma unroll
            for (int nt = 0; nt < 2; nt++) {
                uint32_t rb = (uint32_t)((warpN * 32 + nt * 16 + (quad >> 1) * 8 + r8) * RS) + kbB;
                ldsm4(bh[0][nt], pBh + rb);
                ldsm4(bl[0][nt], pBl + rb);
            }
        }
        #pragma unroll
        for (int slab = 0; slab < 2; slab++) {
            if (slab == 0) {
                uint32_t kbA = 32 + (quad >> 1) * 16;
                uint32_t kbB = 32 + (quad & 1) * 16;
                #pragma unroll
                for (int mt = 0; mt < 2; mt++) {
                    uint32_t ra = (uint32_t)((warpM * 32 + mt * 16 + (quad & 1) * 8 + r8) * RS) + kbA;
                    ldsm4(ah[1][mt], pAh + ra);
                    ldsm4(al[1][mt], pAl + ra);
                }
                #pragma unroll
                for (int nt = 0; nt < 2; nt++) {
                    uint32_t rb = (uint32_t)((warpN * 32 + nt * 16 + (quad >> 1) * 8 + r8) * RS) + kbB;
                    ldsm4(bh[1][nt], pBh + rb);
                    ldsm4(bl[1][nt], pBl + rb);
                }
            }
            #pragma unroll
            for (int mt = 0; mt < 2; mt++)
                #pragma unroll
                for (int nt16 = 0; nt16 < 2; nt16++) {
                    mma_bf16(acc[mt][nt16 * 2 + 0], ah[slab][mt], &bl[slab][nt16][0]);
                    mma_bf16(acc[mt][nt16 * 2 + 0], al[slab][mt], &bh[slab][nt16][0]);
                    mma_bf16(acc[mt][nt16 * 2 + 0], ah[slab][mt], &bh[slab][nt16][0]);
                    mma_bf16(acc[mt][nt16 * 2 + 1], ah[slab][mt], &bl[slab][nt16][2]);
                    mma_bf16(acc[mt][nt16 * 2 + 1], al[slab][mt], &bh[slab][nt16][2]);
                    mma_bf16(acc[mt][nt16 * 2 + 1], ah[slab][mt], &bh[slab][nt16][2]);
                }
        }
    }

    #pragma unroll
    for (int mt = 0; mt < 2; mt++) {
        int rbase = row0 + warpM * 32 + mt * 16 + g;
        #pragma unroll
        for (int nt = 0; nt < 4; nt++) {
            int col = col0 + warpN * 32 + nt * 8 + tg * 2;
            if (col < N) {
                float2 v0 = make_float2(acc[mt][nt][0], acc[mt][nt][1]);
                float2 v1 = make_float2(acc[mt][nt][2], acc[mt][nt][3]);
                if (EPI == 1) {
                    float b0 = bias[col], b1 = bias[col + 1];
                    v0.x = geluf(v0.x + b0); v0.y = geluf(v0.y + b1);
                    v1.x = geluf(v1.x + b0); v1.y = geluf(v1.y + b1);
                }
                if (EPI == 2) {
                    float b0 = bias[col], b1 = bias[col + 1];
                    float2 r0 = *reinterpret_cast<const float2*>(&resid[(long)rbase * N + col]);
                    float2 r1 = *reinterpret_cast<const float2*>(&resid[(long)(rbase + 8) * N + col]);
                    v0.x += b0 + r0.x; v0.y += b1 + r0.y;
                    v1.x += b0 + r1.x; v1.y += b1 + r1.y;
                }
                if (OUTHL) {
                    bf16 h0, h1, l0, l1;
                    split1(v0.x, h0, l0); split1(v0.y, h1, l1);
                    __nv_bfloat162 hp; hp.x = h0; hp.y = h1;
                    __nv_bfloat162 lp; lp.x = l0; lp.y = l1;
                    *reinterpret_cast<uint32_t*>(&Ch[(long)rbase * N + col]) = *reinterpret_cast<uint32_t*>(&hp);
                    *reinterpret_cast<uint32_t*>(&Cl[(long)rbase * N + col]) = *reinterpret_cast<uint32_t*>(&lp);
                    split1(v1.x, h0, l0); split1(v1.y, h1, l1);
                    hp.x = h0; hp.y = h1; lp.x = l0; lp.y = l1;
                    *reinterpret_cast<uint32_t*>(&Ch[(long)(rbase + 8) * N + col]) = *reinterpret_cast<uint32_t*>(&hp);
                    *reinterpret_cast<uint32_t*>(&Cl[(long)(rbase + 8) * N + col]) = *reinterpret_cast<uint32_t*>(&lp);
                } else {
                    *reinterpret_cast<float2*>(&C[(long)rbase * N + col])       = v0;
                    *reinterpret_cast<float2*>(&C[(long)(rbase + 8) * N + col]) = v1;
                }
            }
        }
    }
}

// ===== fused conv + dt + SSM scan (v2: float4-batched smem, 4 steps/barrier) ==
// 96 blocks (dir,b,head) x 256 thr. Producers (tid<192) convolve raw zx cols
// into interleaved smem (pos(n)=(n&3)*16+(n>>2)) so each consumer thread's 16
// B/C values are contiguous -> 8x LDS.128 per step. tid 192..195 produce dt/dA.
// Consumer thread (p=tid>>2, q=tid&3) owns states {4j+q}.
__global__ void __launch_bounds__(256) scan_fused(
        const float* __restrict__ zx, const float* __restrict__ cw,
        const float* __restrict__ cb, const float* __restrict__ dt_bias,
        const float* __restrict__ A_log, const float* __restrict__ Dp_,
        float* __restrict__ yf, float* __restrict__ yb) {
    int blk = blockIdx.x;
    int dir = blk / (BSZn * NHEADSn);
    int rem = blk % (BSZn * NHEADSn);
    int b = rem / NHEADSn, hh = rem % NHEADSn;
    float* y = dir ? yb : yf;
    int tid = threadIdx.x;
    int p = tid >> 2, q = tid & 3;

    __shared__ float sX[2][4][64], sB[2][4][64], sC[2][4][64];
    __shared__ float sdt[2][4], sdA[2][4];

    int lch = tid & 63;
    int role = tid >> 6;               // 0=B, 1=C, 2=x, 3=aux(dt)
    bool isProd = role < 3;
    int convc = (role == 0) ? (DINNER + lch)
              : (role == 1) ? (DINNER + DSTATEn + lch)
              : (hh * HEADDIMn + lch);
    int zcol = DINNER + convc;
    float w0 = 0.f, w1 = 0.f, w2 = 0.f, w3 = 0.f, cbv = 0.f;
    if (isProd) {
        w0 = cw[convc * 4 + 0]; w1 = cw[convc * 4 + 1];
        w2 = cw[convc * 4 + 2]; w3 = cw[convc * 4 + 3];
        cbv = cb[convc];
    }
    bool isDt = (tid >= 192) && (tid < 196);
    int k_dt = tid - 192;
    int dtcol = DINNER + CONVDIM + hh;
    float eA = expf(A_log[hh]);
    float dtb = dt_bias[hh];
    float Dv = Dp_[hh];
    long rowbase = (long)b * SEQn;

    auto ldraw = [&](int s, int col) -> float {
        if (s >= SEQn) return 0.f;
        int t = dir ? (SEQn - 1 - s) : s;
        return zx[(rowbase + t) * DIP + col];
    };

    int ppos = (lch & 3) * 16 + (lch >> 2);   // interleaved position for B/C
    int off = (role == 2) ? lch : ppos;

    // producer pipeline: hist(3 prev raws) + cur(4) + pf(4)
    float h0 = 0.f, h1 = 0.f, h2 = 0.f;
    float cur0 = 0.f, cur1 = 0.f, cur2 = 0.f, cur3 = 0.f;
    float pf0 = 0.f, pf1 = 0.f, pf2 = 0.f, pf3 = 0.f;
    float dcur = 0.f, dpf = 0.f;

    if (isProd) {
        float r0 = ldraw(0, zcol), r1 = ldraw(1, zcol), r2 = ldraw(2, zcol), r3 = ldraw(3, zcol);
        cur0 = ldraw(4, zcol); cur1 = ldraw(5, zcol); cur2 = ldraw(6, zcol); cur3 = ldraw(7, zcol);
        pf0 = ldraw(8, zcol); pf1 = ldraw(9, zcol); pf2 = ldraw(10, zcol); pf3 = ldraw(11, zcol);
        float* dst = (role == 0) ? &sB[0][0][0] : (role == 1) ? &sC[0][0][0] : &sX[0][0][0];
        dst[0 * 64 + off] = siluf(cbv + w3 * r0);
        dst[1 * 64 + off] = siluf(cbv + w2 * r0 + w3 * r1);
        dst[2 * 64 + off] = siluf(cbv + w1 * r0 + w2 * r1 + w3 * r2);
        dst[3 * 64 + off] = siluf(cbv + w0 * r0 + w1 * r1 + w2 * r2 + w3 * r3);
        h0 = r1; h1 = r2; h2 = r3;
    }
    if (isDt) {
        float d0 = ldraw(k_dt, dtcol);
        dcur = ldraw(4 + k_dt, dtcol);
        dpf  = ldraw(8 + k_dt, dtcol);
        float d = d0 + dtb;
        float sp = (d > 20.f) ? d : log1pf(expf(d));
        sdt[0][k_dt] = sp;
        sdA[0][k_dt] = expf(-eA * sp);
    }

    float hst[16];
    #pragma unroll
    for (int j = 0; j < 16; j++) hst[j] = 0.f;

    const int NIT = SEQn / 4;   // 128
    for (int i = 0; i < NIT; i++) {
        __syncthreads();
        int ib = i & 1, nib = ib ^ 1;
        // ---- producers: steps 4(i+1)..4(i+1)+3 into buf nib ----
        if (isProd && i + 1 < NIT) {
            float* dst = (role == 0) ? &sB[nib][0][0] : (role == 1) ? &sC[nib][0][0] : &sX[nib][0][0];
            dst[0 * 64 + off] = siluf(cbv + w0 * h0 + w1 * h1 + w2 * h2 + w3 * cur0);
            dst[1 * 64 + off] = siluf(cbv + w0 * h1 + w1 * h2 + w2 * cur0 + w3 * cur1);
            dst[2 * 64 + off] = siluf(cbv + w0 * h2 + w1 * cur0 + w2 * cur1 + w3 * cur2);
            dst[3 * 64 + off] = siluf(cbv + w0 * cur0 + w1 * cur1 + w2 * cur2 + w3 * cur3);
            h0 = cur1; h1 = cur2; h2 = cur3;
            cur0 = pf0; cur1 = pf1; cur2 = pf2; cur3 = pf3;
            int s = 4 * (i + 3);
            pf0 = ldraw(s, zcol); pf1 = ldraw(s + 1, zcol);
            pf2 = ldraw(s + 2, zcol); pf3 = ldraw(s + 3, zcol);
        }
        if (isDt && i + 1 < NIT) {
            float d = dcur + dtb;
            float sp = (d > 20.f) ? d : log1pf(expf(d));
            sdt[nib][k_dt] = sp;
            sdA[nib][k_dt] = expf(-eA * sp);
            dcur = dpf;
            dpf = ldraw(4 * (i + 3) + k_dt, dtcol);
        }
        // ---- consumers: steps 4i..4i+3 from buf ib ----
        #pragma unroll
        for (int sp_ = 0; sp_ < 4; sp_++) {
            int s = 4 * i + sp_;
            float cdt = sdt[ib][sp_], cdA = sdA[ib][sp_];
            float cx = sX[ib][sp_][p];
            float bv[16], cv[16];
            *reinterpret_cast<float4*>(&bv[0])  = *reinterpret_cast<const float4*>(&sB[ib][sp_][q * 16]);
            *reinterpret_cast<float4*>(&bv[4])  = *reinterpret_cast<const float4*>(&sB[ib][sp_][q * 16 + 4]);
            *reinterpret_cast<float4*>(&bv[8])  = *reinterpret_cast<const float4*>(&sB[ib][sp_][q * 16 + 8]);
            *reinterpret_cast<float4*>(&bv[12]) = *reinterpret_cast<const float4*>(&sB[ib][sp_][q * 16 + 12]);
            *reinterpret_cast<float4*>(&cv[0])  = *reinterpret_cast<const float4*>(&sC[ib][sp_][q * 16]);
            *reinterpret_cast<float4*>(&cv[4])  = *reinterpret_cast<const float4*>(&sC[ib][sp_][q * 16 + 4]);
            *reinterpret_cast<float4*>(&cv[8])  = *reinterpret_cast<const float4*>(&sC[ib][sp_][q * 16 + 8]);
            *reinterpret_cast<float4*>(&cv[12]) = *reinterpret_cast<const float4*>(&sC[ib][sp_][q * 16 + 12]);
            float c1 = cdt * cx;
            float yv0 = (q == 0) ? Dv * cx : 0.f;
            float yv1 = 0.f, yv2 = 0.f, yv3 = 0.f;
            #pragma unroll
            for (int j = 0; j < 16; j += 4) {
                hst[j]     = cdA * hst[j]     + c1 * bv[j];     yv0 += hst[j]     * cv[j];
                hst[j + 1] = cdA * hst[j + 1] + c1 * bv[j + 1]; yv1 += hst[j + 1] * cv[j + 1];
                hst[j + 2] = cdA * hst[j + 2] + c1 * bv[j + 2]; yv2 += hst[j + 2] * cv[j + 2];
                hst[j + 3] = cdA * hst[j + 3] + c1 * bv[j + 3]; yv3 += hst[j + 3] * cv[j + 3];
            }
            float yv = (yv0 + yv1) + (yv2 + yv3);
            yv += __shfl_xor_sync(0xffffffffu, yv, 1);
            yv += __shfl_xor_sync(0xffffffffu, yv, 2);
            if (q == 0) {
                int t = dir ? (SEQn - 1 - s) : s;
                y[(rowbase + t) * DINNER + hh * HEADDIMn + p] = yv;
            }
        }
    }
}

// ------ gate + RMSNorm + sum -> bf16 hi/lo planes ----------------
__global__ void gatenorm_kernel(const float* __restrict__ yf, const float* __restrict__ yb,
                                const float* __restrict__ zx, const float* __restrict__ nw,
                                bf16* __restrict__ oh, bf16* __restrict__ ol) {
    int row = blockIdx.x;
    int tid = threadIdx.x;
    const float* z = zx + (long)row * DIP;
    float gf[6], gb[6], ssf = 0.f, ssb = 0.f;
    #pragma unroll
    for (int i = 0; i < 6; i++) {
        int c = tid + i * 256;
        float s = siluf(z[c]);
        float a = yf[(long)row * DINNER + c] * s;
        float d = yb[(long)row * DINNER + c] * s;
        gf[i] = a; gb[i] = d;
        ssf += a * a; ssb += d * d;
    }
    __shared__ float r1[8], r2[8], bres[2];
    float w1 = warp_sum(ssf), w2 = warp_sum(ssb);
    int lane = tid & 31, wid = tid >> 5;
    if (lane == 0) { r1[wid] = w1; r2[wid] = w2; }
    __syncthreads();
    if (tid == 0) {
        float a = 0.f, c = 0.f;
        #pragma unroll
        for (int i = 0; i < 8; i++) { a += r1[i]; c += r2[i]; }
        bres[0] = a; bres[1] = c;
    }
    __syncthreads();
    float rf = rsqrtf(bres[0] * (1.f / DINNER) + EPSV);
    float rb = rsqrtf(bres[1] * (1.f / DINNER) + EPSV);
    #pragma unroll
    for (int i = 0; i < 6; i++) {
        int c = tid + i * 256;
        float o = (gf[i] * rf + gb[i] * rb) * nw[c];
        bf16 h, l; split1(o, h, l);
        oh[(long)row * DINNER + c] = h;
        ol[(long)row * DINNER + c] = l;
    }
}

// ---------------- launch ----------------
extern "C" void kernel_launch(void* const* d_in, const int* in_sizes, int n_in,
                              void* d_out, int out_size) {
    const float* x        = (const float*)d_in[0];
    const float* in_proj  = (const float*)d_in[1];
    const float* conv_w   = (const float*)d_in[2];
    const float* conv_b   = (const float*)d_in[3];
    const float* dt_bias  = (const float*)d_in[4];
    const float* A_log    = (const float*)d_in[5];
    const float* D_param  = (const float*)d_in[6];
    const float* norm_w   = (const float*)d_in[7];
    const float* out_proj = (const float*)d_in[8];
    const float* ln1_w    = (const float*)d_in[9];
    const float* ln1_b    = (const float*)d_in[10];
    const float* ln2_w    = (const float*)d_in[11];
    const float* ln2_b    = (const float*)d_in[12];
    const float* ff_w1    = (const float*)d_in[13];
    const float* ff_b1    = (const float*)d_in[14];
    const float* ff_w2    = (const float*)d_in[15];
    const float* ff_b2    = (const float*)d_in[16];
    float* out = (float*)d_out;

    float *p_zx, *p_yf, *p_yb, *p_mi;
    bf16 *p_xnh, *p_xnl, *p_ysh, *p_ysl, *p_mh, *p_ml, *p_h1h, *p_h1l;
    bf16 *p_wip_h, *p_wip_l, *p_wop_h, *p_wop_l, *p_w1_h, *p_w1_l, *p_w2_h, *p_w2_l;
    cudaGetSymbolAddress((void**)&p_zx,   g_zx);
    cudaGetSymbolAddress((void**)&p_yf,   g_yf);
    cudaGetSymbolAddress((void**)&p_yb,   g_yb);
    cudaGetSymbolAddress((void**)&p_mi,   g_mi);
    cudaGetSymbolAddress((void**)&p_xnh,  g_xnh);
    cudaGetSymbolAddress((void**)&p_xnl,  g_xnl);
    cudaGetSymbolAddress((void**)&p_ysh,  g_ysh);
    cudaGetSymbolAddress((void**)&p_ysl,  g_ysl);
    cudaGetSymbolAddress((void**)&p_mh,   g_mh);
    cudaGetSymbolAddress((void**)&p_ml,   g_ml);
    cudaGetSymbolAddress((void**)&p_h1h,  g_h1h);
    cudaGetSymbolAddress((void**)&p_h1l,  g_h1l);
    cudaGetSymbolAddress((void**)&p_wip_h, g_wip_h);
    cudaGetSymbolAddress((void**)&p_wip_l, g_wip_l);
    cudaGetSymbolAddress((void**)&p_wop_h, g_wop_h);
    cudaGetSymbolAddress((void**)&p_wop_l, g_wop_l);
    cudaGetSymbolAddress((void**)&p_w1_h,  g_w1_h);
    cudaGetSymbolAddress((void**)&p_w1_l,  g_w1_l);
    cudaGetSymbolAddress((void**)&p_w2_h,  g_w2_h);
    cudaGetSymbolAddress((void**)&p_w2_l,  g_w2_l);

    cudaFuncSetAttribute(gemm_bf16p<0,0>, cudaFuncAttributeMaxDynamicSharedMemorySize, GEMM_SMEM);
    cudaFuncSetAttribute(gemm_bf16p<1,1>, cudaFuncAttributeMaxDynamicSharedMemorySize, GEMM_SMEM);
    cudaFuncSetAttribute(gemm_bf16p<2,0>, cudaFuncAttributeMaxDynamicSharedMemorySize, GEMM_SMEM);

    // #0 ln1(x) -> xn planes
    ln_hl_kernel<<<BT, 256>>>(x, ln1_w, ln1_b, p_xnh, p_xnl);
    // #1 split in_proj
    wsplit_kernel<<<(DIP*DMODEL/4 + 255) / 256, 256>>>(in_proj,  p_wip_h, p_wip_l, DIP*DMODEL/4);
    // #2 zxbcdt = xn @ in_proj^T   [1024, 3224]
    gemm_bf16p<0,0><<<dim3((DIP + 63) / 64, BT / 128), 256, GEMM_SMEM>>>(
        p_xnh, p_xnl, p_wip_h, p_wip_l, nullptr, nullptr, p_zx, nullptr, nullptr, BT, DIP, DMODEL);
    // #3 fused conv + dt + SSM scan   <-- ncu capture slot
    scan_fused<<<2 * BSZn * NHEADSn, 256>>>(p_zx, conv_w, conv_b, dt_bias, A_log, D_param, p_yf, p_yb);
    // #4 gate + RMSNorm per dir + sum -> ysum planes
    gatenorm_kernel<<<BT, 256>>>(p_yf, p_yb, p_zx, norm_w, p_ysh, p_ysl);
    // #5 split out_proj
    wsplit_kernel<<<(DMODEL*DINNER/4 + 255) / 256, 256>>>(out_proj, p_wop_h, p_wop_l, DMODEL*DINNER/4);
    // #6 mi = ysum @ out_proj^T  [1024, 768]
    gemm_bf16p<0,0><<<dim3(DMODEL / 64, BT / 128), 256, GEMM_SMEM>>>(
        p_ysh, p_ysl, p_wop_h, p_wop_l, nullptr, nullptr, p_mi, nullptr, nullptr, BT, DMODEL, DINNER);
    // #7 ln2 -> m planes
    ln_hl_kernel<<<BT, 256>>>(p_mi, ln2_w, ln2_b, p_mh, p_ml);
    // #8 split ff_w1
    wsplit_kernel<<<(DFF*DMODEL/4 + 255) / 256, 256>>>(ff_w1, p_w1_h, p_w1_l, DFF*DMODEL/4);
    // #9 h1 = gelu(m @ ff_w1^T + b1) -> h1 planes  [1024, 3072]
    gemm_bf16p<1,1><<<dim3(DFF / 64, BT / 128), 256, GEMM_SMEM>>>(
        p_mh, p_ml, p_w1_h, p_w1_l, ff_b1, nullptr, nullptr, p_h1h, p_h1l, BT, DFF, DMODEL);
    // #10 split ff_w2
    wsplit_kernel<<<(DMODEL*DFF/4 + 255) / 256, 256>>>(ff_w2, p_w2_h, p_w2_l, DMODEL*DFF/4);
    // #11 out = h1 @ ff_w2^T + b2 + x
    gemm_bf16p<2,0><<<dim3(DMODEL / 64, BT / 128), 256, GEMM_SMEM>>>(
        p_h1h, p_h1l, p_w2_h, p_w2_l, ff_b2, x, out, nullptr, nullptr, BT, DMODEL, DFF);
}